// round 11
// baseline (speedup 1.0000x reference)
#include <cuda_runtime.h>
#include <cuda_bf16.h>
#include <stdint.h>

// Problem constants
#define B_FEAT 128
#define U_UNITS 100000
#define K_NBR 500
#define N_RUNS 10
#define N_PAIRS 124750.0
#define T2 32             // pair tile edge
#define NTP2 136          // 16*17/2 lower-tri tile pairs (incl diagonal)
#define TILE_TASKS (NTP2 * N_RUNS)   // 1360
#define YSTRIDE 132       // float row stride: 132 mod 32 == 4 -> conflict-free frags
#define GRID_F 444        // 148 SMs x 3 blocks, co-residency guaranteed
#define NWARPS 8
#define TOT_WARPS (GRID_F * NWARPS)  // 3552
#define COL_TASKS (N_RUNS * K_NBR)   // 5000

// Scratch (device globals; no allocation allowed)
__device__ float  g_Y[N_RUNS][K_NBR][B_FEAT];   // normalized, tf32-rounded
__device__ float2 g_P[N_RUNS][K_NBR];           // gathered positions
__device__ double g_acc[N_RUNS][5];             // zero-init; reset by finalizer
__device__ int    g_bar  = 0;                   // grid barrier (reset by finalizer)
__device__ int    g_done = 0;                   // finalize counter (reset by finalizer)

struct Choice { int v[N_RUNS]; };

// ---------------------------------------------------------------------------
// ONE fused kernel: prep (per-warp) -> grid barrier -> MMA tiles -> finalize
// ---------------------------------------------------------------------------
__global__ __launch_bounds__(256) void fused_kernel(
    const float* __restrict__ feat,
    const float* __restrict__ pos,
    const int*   __restrict__ nbh,
    Choice ch,
    float* __restrict__ out)
{
    extern __shared__ char sraw[];
    float*  Ys = (float*)sraw;                   // Yi [32][132]
    float*  Yt = Ys + T2 * YSTRIDE;              // Yj [32][132]
    float2* Pi = (float2*)(Yt + T2 * YSTRIDE);
    float2* Pj = Pi + T2;

    int tid  = threadIdx.x;
    int bid  = blockIdx.x;
    int lane = tid & 31;
    int w    = tid >> 5;

    // ---------------- Phase A: prep, one (run,u) column per warp -----------
    for (int task = bid * NWARPS + w; task < COL_TASKS; task += TOT_WARPS) {
        int run = task / K_NBR;
        int u   = task - run * K_NBR;
        int ind = __ldg(&nbh[ch.v[run] * K_NBR + u]);

        float v[4];
        #pragma unroll
        for (int k = 0; k < 4; k++)
            v[k] = __ldg(&feat[(lane + 32 * k) * U_UNITS + ind]);

        float s = v[0] + v[1] + v[2] + v[3];
        #pragma unroll
        for (int o = 16; o > 0; o >>= 1) s += __shfl_xor_sync(0xFFFFFFFFu, s, o);
        float mean = s * (1.0f / B_FEAT);

        float c[4], q = 0.f;
        #pragma unroll
        for (int k = 0; k < 4; k++) { c[k] = v[k] - mean; q += c[k] * c[k]; }
        #pragma unroll
        for (int o = 16; o > 0; o >>= 1) q += __shfl_xor_sync(0xFFFFFFFFu, q, o);
        float inv = rsqrtf(q);

        #pragma unroll
        for (int k = 0; k < 4; k++) {
            uint32_t ytf;
            float y = c[k] * inv;
            asm("cvt.rna.tf32.f32 %0, %1;" : "=r"(ytf) : "f"(y));
            g_Y[run][u][lane + 32 * k] = __uint_as_float(ytf);
        }
        if (lane == 0)
            g_P[run][u] = make_float2(__ldg(&pos[ind * 2]), __ldg(&pos[ind * 2 + 1]));
    }

    // ---------------- Phase B: software grid barrier -----------------------
    __threadfence();            // publish this thread's g_Y/g_P writes
    __syncthreads();
    if (tid == 0) {
        atomicAdd(&g_bar, 1);
        volatile int* vb = &g_bar;
        while (*vb < GRID_F) __nanosleep(64);
    }
    __syncthreads();

    // ---------------- Phase C: pair tiles, grid-stride ---------------------
    int g4 = lane >> 2, q4 = lane & 3;
    int wy = w >> 2, wx = w & 3;          // 2x4 warp grid: rows wy*16, cols wx*8

    for (int tt = bid; tt < TILE_TASKS; tt += GRID_F) {
        int run = tt / NTP2;
        int t   = tt - run * NTP2;
        int ti = 0;
        while ((ti + 1) * (ti + 2) / 2 <= t) ti++;
        int tj = t - ti * (ti + 1) / 2;
        int i0 = ti * T2, j0 = tj * T2;

        __syncthreads();   // previous iteration's readers done before restage

        for (int idx = tid; idx < T2 * 32; idx += 256) {
            int r = idx >> 5, c = idx & 31;
            int gi = i0 + r, gj = j0 + r;
            ((float4*)(Ys + r * YSTRIDE))[c] =
                (gi < K_NBR) ? ((const float4*)g_Y[run][gi])[c] : make_float4(0, 0, 0, 0);
            ((float4*)(Yt + r * YSTRIDE))[c] =
                (gj < K_NBR) ? ((const float4*)g_Y[run][gj])[c] : make_float4(0, 0, 0, 0);
        }
        if (tid < T2) {
            Pi[tid] = (i0 + tid < K_NBR) ? g_P[run][i0 + tid] : make_float2(0, 0);
        } else if (tid < 2 * T2) {
            int k = tid - T2;
            Pj[k] = (j0 + k < K_NBR) ? g_P[run][j0 + k] : make_float2(0, 0);
        }
        __syncthreads();

        const float* Arow0 = Ys + (wy * 16 + g4) * YSTRIDE;
        const float* Brow  = Yt + (wx * 8 + g4) * YSTRIDE;

        float acc[2][4];
        #pragma unroll
        for (int h = 0; h < 2; h++)
            #pragma unroll
            for (int e = 0; e < 4; e++) acc[h][e] = 0.f;

        #pragma unroll
        for (int ks = 0; ks < 8; ks++) {
            #pragma unroll
            for (int h = 0; h < 2; h++) {
                int k0 = (h * 8 + ks) * 8;
                uint32_t a0 = __float_as_uint(Arow0[k0 + q4]);
                uint32_t a1 = __float_as_uint(Arow0[8 * YSTRIDE + k0 + q4]);
                uint32_t a2 = __float_as_uint(Arow0[k0 + q4 + 4]);
                uint32_t a3 = __float_as_uint(Arow0[8 * YSTRIDE + k0 + q4 + 4]);
                uint32_t b0 = __float_as_uint(Brow[k0 + q4]);
                uint32_t b1 = __float_as_uint(Brow[k0 + q4 + 4]);
                asm volatile(
                    "mma.sync.aligned.m16n8k8.row.col.f32.tf32.tf32.f32 "
                    "{%0,%1,%2,%3}, {%4,%5,%6,%7}, {%8,%9}, {%0,%1,%2,%3};"
                    : "+f"(acc[h][0]), "+f"(acc[h][1]), "+f"(acc[h][2]), "+f"(acc[h][3])
                    : "r"(a0), "r"(a1), "r"(a2), "r"(a3), "r"(b0), "r"(b1));
            }
        }

        // epilogue: thread owns D rows {wy*16+g4, +8}, cols {wx*8+2*q4, +1}
        float sr = 0.f, sd = 0.f, srd = 0.f, srr = 0.f, sdd = 0.f;
        int r0l = wy * 16 + g4;
        int c0l = wx * 8 + 2 * q4;
        #pragma unroll
        for (int e = 0; e < 4; e++) {
            int li = r0l + (e >> 1) * 8;
            int lj = c0l + (e & 1);
            int gi = i0 + li, gj = j0 + lj;
            if (gi < K_NBR && gj < K_NBR && gi > gj) {
                float dot = acc[0][e] + acc[1][e];
                float dx = Pi[li].x - Pj[lj].x;
                float dy = Pi[li].y - Pj[lj].y;
                float ds = 1.0f / (sqrtf(dx * dx + dy * dy) + 1.0f);
                sr  += dot;
                sd  += ds;
                srd += dot * ds;
                srr += dot * dot;
                sdd += ds * ds;
            }
        }

        // warp reduce 5 sums, lane0 -> double atomics (no block reduce, no g_part)
        #pragma unroll
        for (int off = 16; off > 0; off >>= 1) {
            sr  += __shfl_down_sync(0xFFFFFFFFu, sr,  off);
            sd  += __shfl_down_sync(0xFFFFFFFFu, sd,  off);
            srd += __shfl_down_sync(0xFFFFFFFFu, srd, off);
            srr += __shfl_down_sync(0xFFFFFFFFu, srr, off);
            sdd += __shfl_down_sync(0xFFFFFFFFu, sdd, off);
        }
        if (lane == 0) {
            atomicAdd(&g_acc[run][0], (double)sr);
            atomicAdd(&g_acc[run][1], (double)sd);
            atomicAdd(&g_acc[run][2], (double)srd);
            atomicAdd(&g_acc[run][3], (double)srr);
            atomicAdd(&g_acc[run][4], (double)sdd);
        }
    }

    // ---------------- Phase D: last-block finalize -------------------------
    __shared__ int isLast;
    if (tid == 0) {
        __threadfence();
        int done = atomicAdd(&g_done, 1);
        isLast = (done == GRID_F - 1) ? 1 : 0;
    }
    __syncthreads();
    if (!isLast) return;

    __shared__ double lsum[N_RUNS];
    if (tid < N_RUNS) {
        double Sr  = g_acc[tid][0], Sd  = g_acc[tid][1], Srd = g_acc[tid][2];
        double Srr = g_acc[tid][3], Sdd = g_acc[tid][4];
        double num = Srd - Sr * Sd / N_PAIRS;
        double den = sqrt((Srr - Sr * Sr / N_PAIRS) * (Sdd - Sd * Sd / N_PAIRS));
        lsum[tid] = (1.0 - num / den) * 0.5;
    }
    __syncthreads();
    if (tid == 0) {
        double s = 0;
        #pragma unroll
        for (int i = 0; i < N_RUNS; i++) s += lsum[i];
        out[0] = (float)(s / N_RUNS);
    }
    // reset state for next graph replay (after all reads above)
    __syncthreads();
    if (tid < N_RUNS * 5) ((double*)g_acc)[tid] = 0.0;
    if (tid == 0) { g_done = 0; g_bar = 0; }
}

// ---------------------------------------------------------------------------
// Host-side JAX threefry2x32: choice = randint(key(42),(10,),0,100)
// ---------------------------------------------------------------------------
static inline uint32_t rotl32(uint32_t x, int r) { return (x << r) | (x >> (32 - r)); }

static void threefry2x32(uint32_t k0, uint32_t k1, uint32_t c0, uint32_t c1,
                         uint32_t* o0, uint32_t* o1) {
    uint32_t ks0 = k0, ks1 = k1, ks2 = k0 ^ k1 ^ 0x1BD11BDAu;
    uint32_t x0 = c0 + ks0, x1 = c1 + ks1;
    const int rotA[4] = {13, 15, 26, 6};
    const int rotB[4] = {17, 29, 16, 24};
#define TF_ROUND4(R) do { for (int _i = 0; _i < 4; _i++) { \
        x0 += x1; x1 = rotl32(x1, (R)[_i]); x1 ^= x0; } } while (0)
    TF_ROUND4(rotA); x0 += ks1; x1 += ks2 + 1;
    TF_ROUND4(rotB); x0 += ks2; x1 += ks0 + 2;
    TF_ROUND4(rotA); x0 += ks0; x1 += ks1 + 3;
    TF_ROUND4(rotB); x0 += ks1; x1 += ks2 + 4;
    TF_ROUND4(rotA); x0 += ks2; x1 += ks0 + 5;
#undef TF_ROUND4
    *o0 = x0; *o1 = x1;
}

extern "C" void kernel_launch(void* const* d_in, const int* in_sizes, int n_in,
                              void* d_out, int out_size) {
    const float* feat = (const float*)d_in[0];
    const float* pos  = (const float*)d_in[1];
    const int*   nbh  = (const int*)d_in[2];

    uint32_t bits[N_RUNS];
    for (uint32_t i = 0; i < 5; i++) {
        uint32_t o0, o1;
        threefry2x32(0u, 42u, i, i + 5u, &o0, &o1);
        bits[i] = o0;
        bits[i + 5] = o1;
    }
    Choice ch;
    for (int i = 0; i < N_RUNS; i++) {
        uint32_t b = bits[i];
        uint32_t hi = b >> 16, lo = b & 0xFFFFu;
        ch.v[i] = (int)(((hi % 100u) * 96u + (lo % 100u)) % 100u);
    }

    const int SMEM = 2 * T2 * YSTRIDE * (int)sizeof(float) + 2 * T2 * (int)sizeof(float2);
    cudaFuncSetAttribute(fused_kernel, cudaFuncAttributeMaxDynamicSharedMemorySize, SMEM);

    fused_kernel<<<GRID_F, 256, SMEM>>>(feat, pos, nbh, ch, (float*)d_out);
}